// round 1
// baseline (speedup 1.0000x reference)
#include <cuda_runtime.h>
#include <cstdint>

// Problem constants
#define NUM_FRAME 300
#define LEN_FRAME 512
#define T_LEN     20000
#define NBF       200          // 4 * 50
#define NLAG      256          // LEN_FRAME / 2

// Packed fp32x2 FMA (sm_100+ PTX, Blackwell FFMA2). Lanes = the two channels.
__device__ __forceinline__ unsigned long long ffma2(unsigned long long a,
                                                    unsigned long long b,
                                                    unsigned long long c) {
    unsigned long long d;
    asm("fma.rn.f32x2 %0, %1, %2, %3;" : "=l"(d) : "l"(a), "l"(b), "l"(c));
    return d;
}

__device__ __forceinline__ float2 ull_as_f2(unsigned long long u) {
    float2 f;
    f.x = __uint_as_float((unsigned int)(u & 0xffffffffull));
    f.y = __uint_as_float((unsigned int)(u >> 32));
    return f;
}

// One block per (bf, frame). 256 threads.
//  - smem sAB[768]: windowed frame, channels packed as float2, tail duplicated
//    (sAB[512+i] = sAB[i]) so circular access n+l (< 768) is linear.
//  - thread tid: partition p = tid>>6 owns n in [128p, 128p+128),
//    q = tid&63 owns lags 4q..4q+3. Sliding 8-register window over the
//    shifted stream gives 16 FFMA2 per 4 smem vector loads.
//  - cross-partition reduction in smem, then relu / sqrt-norm / channel mean.
__global__ __launch_bounds__(256, 6)
void acg_kernel(const float2* __restrict__ in, float* __restrict__ out) {
    __shared__ float2 sAB[768];
    __shared__ unsigned long long red[4 * NLAG];
    __shared__ float2 snorm;

    const int frame = blockIdx.x;
    const int bf    = blockIdx.y;
    const int tid   = threadIdx.x;

    // starts = linspace(0, T-L, 300).astype(int64)  ==  (i*(T-L))/299 exactly
    const int start = (frame * (T_LEN - LEN_FRAME)) / (NUM_FRAME - 1);

    // ---- load + Hann window (channels packed in float2) ----
    const float2* base = in + (size_t)bf * T_LEN + start;
    #pragma unroll
    for (int i = tid; i < LEN_FRAME; i += 256) {
        float2 v = base[i];
        float w = 0.5f - 0.5f * cospif((float)i * (1.0f / 256.0f));
        float2 sv = make_float2(v.x * w, v.y * w);
        sAB[i] = sv;
        if (i < NLAG) sAB[LEN_FRAME + i] = sv;   // duplicated tail for circular wrap
    }
    __syncthreads();

    // ---- register-tiled autocorrelation ----
    const ulonglong2* s2 = (const ulonglong2*)sAB;   // 2 float2 per 16B vector
    const int p  = tid >> 6;
    const int q  = tid & 63;
    const int n0 = p << 7;   // 128*p
    const int L  = q << 2;   // 4*q

    unsigned long long acc0 = 0ull, acc1 = 0ull, acc2 = 0ull, acc3 = 0ull;

    int m = n0 + L;          // shifted-stream cursor (multiple of 4)
    ulonglong2 t0 = s2[m >> 1];
    ulonglong2 t1 = s2[(m >> 1) + 1];
    unsigned long long w0 = t0.x, w1 = t0.y, w2 = t1.x, w3 = t1.y;

    #pragma unroll 8
    for (int it = 0; it < 32; ++it) {
        const int n = n0 + (it << 2);
        // next 4 shifted values: s[m+4 .. m+7]
        ulonglong2 tw  = s2[(m + 4) >> 1];
        ulonglong2 tw2 = s2[((m + 4) >> 1) + 1];
        const unsigned long long w4 = tw.x, w5 = tw.y, w6 = tw2.x, w7 = tw2.y;
        // 4 base values (warp-broadcast): s[n .. n+3]
        ulonglong2 tb  = s2[n >> 1];
        ulonglong2 tb2 = s2[(n >> 1) + 1];

        // acc_k += s[n+j] * s[n+j+L+k]   (w[idx] = s[m+idx] = s[n+L+idx])
        acc0 = ffma2(tb.x,  w0, acc0); acc1 = ffma2(tb.x,  w1, acc1);
        acc2 = ffma2(tb.x,  w2, acc2); acc3 = ffma2(tb.x,  w3, acc3);
        acc0 = ffma2(tb.y,  w1, acc0); acc1 = ffma2(tb.y,  w2, acc1);
        acc2 = ffma2(tb.y,  w3, acc2); acc3 = ffma2(tb.y,  w4, acc3);
        acc0 = ffma2(tb2.x, w2, acc0); acc1 = ffma2(tb2.x, w3, acc1);
        acc2 = ffma2(tb2.x, w4, acc2); acc3 = ffma2(tb2.x, w5, acc3);
        acc0 = ffma2(tb2.y, w3, acc0); acc1 = ffma2(tb2.y, w4, acc1);
        acc2 = ffma2(tb2.y, w5, acc2); acc3 = ffma2(tb2.y, w6, acc3);

        w0 = w4; w1 = w5; w2 = w6; w3 = w7;
        m += 4;
    }

    // ---- cross-partition reduction ----
    {
        unsigned long long* r = &red[p * NLAG + L];
        r[0] = acc0; r[1] = acc1; r[2] = acc2; r[3] = acc3;
    }
    __syncthreads();

    float2 a = ull_as_f2(red[tid]);
    float2 b1 = ull_as_f2(red[NLAG + tid]);
    float2 b2 = ull_as_f2(red[2 * NLAG + tid]);
    float2 b3 = ull_as_f2(red[3 * NLAG + tid]);
    float chA = a.x + b1.x + b2.x + b3.x;
    float chB = a.y + b1.y + b2.y + b3.y;

    // relu
    chA = fmaxf(chA, 0.0f);
    chB = fmaxf(chB, 0.0f);

    // lag-0 norms (thread 0 owns lag 0)
    if (tid == 0) snorm = make_float2(chA, chB);
    __syncthreads();

    float nA = snorm.x; nA = (nA == 0.0f) ? 1.0f : nA;
    float nB = snorm.y; nB = (nB == 0.0f) ? 1.0f : nB;

    const float o = 0.5f * (chA * rsqrtf(nA) + chB * rsqrtf(nB));
    out[((size_t)bf * NUM_FRAME + frame) * NLAG + tid] = o;
}

extern "C" void kernel_launch(void* const* d_in, const int* in_sizes, int n_in,
                              void* d_out, int out_size) {
    (void)in_sizes; (void)n_in; (void)out_size;
    const float2* in = (const float2*)d_in[0];
    float* out = (float*)d_out;
    dim3 grid(NUM_FRAME, NBF);
    acg_kernel<<<grid, 256>>>(in, out);
}

// round 3
// speedup vs baseline: 1.4845x; 1.4845x over previous
#include <cuda_runtime.h>
#include <cstdint>

// Problem constants
#define NUM_FRAME 300
#define LEN_FRAME 512
#define T_LEN     20000
#define NBF       200          // 4 * 50
#define NLAG      256          // LEN_FRAME / 2
#define NPART     8            // warps per block = n-partitions

// Packed fp32x2 FMA (sm_100+ PTX, Blackwell FFMA2). Lanes = the two channels.
__device__ __forceinline__ unsigned long long ffma2(unsigned long long a,
                                                    unsigned long long b,
                                                    unsigned long long c) {
    unsigned long long d;
    asm("fma.rn.f32x2 %0, %1, %2, %3;" : "=l"(d) : "l"(a), "l"(b), "l"(c));
    return d;
}

__device__ __forceinline__ float2 ull_as_f2(unsigned long long u) {
    float2 f;
    f.x = __uint_as_float((unsigned int)(u & 0xffffffffull));
    f.y = __uint_as_float((unsigned int)(u >> 32));
    return f;
}

// Swizzled 16B-unit load: permutes bank group (u&7) by XOR with (u>>3)&7 so
// lane strides of 2 or 4 units hit all 8 bank groups per 8-lane phase.
__device__ __forceinline__ ulonglong2 ldu(const ulonglong2* __restrict__ s, int u) {
    return s[u ^ ((u >> 3) & 7)];
}

// One block per (bf, frame). 256 threads = 8 warps.
//  - sAB: 768 channel-packed (float2-as-ull) windowed samples, tail-duplicated
//    for circular wrap, stored XOR-swizzled at 16B-unit granularity.
//  - warp p owns n in [64p, 64p+64); lane q owns lags 8q..8q+7.
//    Sliding 12-register window: 32 FFMA2 per 4 LDS.128 (2 strided conflict-free
//    after swizzle + 2 warp-broadcast).
//  - cross-warp reduction in smem, then relu / sqrt-norm / channel mean.
__global__ __launch_bounds__(256, 4)
void acg_kernel(const float2* __restrict__ in, float* __restrict__ out) {
    __shared__ ulonglong2 sAB[384];                 // 768 values, swizzled
    __shared__ unsigned long long red[NPART * NLAG];
    __shared__ float2 snorm;

    const int frame = blockIdx.x;
    const int bf    = blockIdx.y;
    const int tid   = threadIdx.x;

    // starts = linspace(0, T-L, 300).astype(int64)  ==  (i*(T-L))/299 exactly
    const int start = (frame * (T_LEN - LEN_FRAME)) / (NUM_FRAME - 1);

    // ---- load + Hann window, swizzled store ----
    const float2* base = in + (size_t)bf * T_LEN + start;
    unsigned long long* s8 = (unsigned long long*)sAB;
    #pragma unroll
    for (int i = tid; i < LEN_FRAME; i += 256) {
        float2 v = base[i];
        float w = 0.5f - 0.5f * cospif((float)i * (1.0f / 256.0f));
        unsigned long long pv =
            ((unsigned long long)__float_as_uint(v.y * w) << 32) |
            __float_as_uint(v.x * w);
        int u = i >> 1;
        s8[((u ^ ((u >> 3) & 7)) << 1) | (i & 1)] = pv;
        if (i < NLAG) {                              // duplicated circular tail
            int i2 = i + LEN_FRAME;
            int u2 = i2 >> 1;
            s8[((u2 ^ ((u2 >> 3) & 7)) << 1) | (i2 & 1)] = pv;
        }
    }
    __syncthreads();

    // ---- register-tiled autocorrelation: 8 lags/thread, 4-n steps ----
    const int p  = tid >> 5;       // warp = partition
    const int q  = tid & 31;       // lane = lag octet
    const int L  = q << 3;         // first lag
    const int e0 = (p << 5) + (q << 2);   // unit index of s[64p + 8q]
    const int bu0 = p << 5;               // unit index of s[64p]

    unsigned long long acc[8];
    #pragma unroll
    for (int k = 0; k < 8; ++k) acc[k] = 0ull;

    unsigned long long w[12];
    {   // prologue: w0..w7 = s[m0 .. m0+7]  (units e0..e0+3)
        ulonglong2 t0 = ldu(sAB, e0 + 0);
        ulonglong2 t1 = ldu(sAB, e0 + 1);
        ulonglong2 t2 = ldu(sAB, e0 + 2);
        ulonglong2 t3 = ldu(sAB, e0 + 3);
        w[0] = t0.x; w[1] = t0.y; w[2] = t1.x; w[3] = t1.y;
        w[4] = t2.x; w[5] = t2.y; w[6] = t3.x; w[7] = t3.y;
    }

    #pragma unroll
    for (int it = 0; it < 16; ++it) {
        // strided: w8..w11 = s[m+8 .. m+11]  (conflict-free after swizzle)
        ulonglong2 t0 = ldu(sAB, e0 + 2 * it + 4);
        ulonglong2 t1 = ldu(sAB, e0 + 2 * it + 5);
        w[8] = t0.x; w[9] = t0.y; w[10] = t1.x; w[11] = t1.y;
        // broadcast: b0..b3 = s[n .. n+3]
        ulonglong2 tb0 = ldu(sAB, bu0 + 2 * it);
        ulonglong2 tb1 = ldu(sAB, bu0 + 2 * it + 1);
        unsigned long long b[4] = { tb0.x, tb0.y, tb1.x, tb1.y };

        #pragma unroll
        for (int j = 0; j < 4; ++j)
            #pragma unroll
            for (int k = 0; k < 8; ++k)
                acc[k] = ffma2(b[j], w[j + k], acc[k]);

        #pragma unroll
        for (int r = 0; r < 8; ++r) w[r] = w[r + 4];
    }

    // ---- cross-partition reduction ----
    {
        unsigned long long* r = &red[(p << 8) + L];
        #pragma unroll
        for (int k = 0; k < 8; ++k) r[k] = acc[k];
    }
    __syncthreads();

    float chA = 0.0f, chB = 0.0f;
    #pragma unroll
    for (int j = 0; j < NPART; ++j) {
        float2 v = ull_as_f2(red[(j << 8) + tid]);
        chA += v.x; chB += v.y;
    }

    // relu
    chA = fmaxf(chA, 0.0f);
    chB = fmaxf(chB, 0.0f);

    // lag-0 norms (thread 0 owns lag 0)
    if (tid == 0) snorm = make_float2(chA, chB);
    __syncthreads();

    float nA = snorm.x; nA = (nA == 0.0f) ? 1.0f : nA;
    float nB = snorm.y; nB = (nB == 0.0f) ? 1.0f : nB;

    const float o = 0.5f * (chA * rsqrtf(nA) + chB * rsqrtf(nB));
    out[((size_t)bf * NUM_FRAME + frame) * NLAG + tid] = o;
}

extern "C" void kernel_launch(void* const* d_in, const int* in_sizes, int n_in,
                              void* d_out, int out_size) {
    (void)in_sizes; (void)n_in; (void)out_size;
    const float2* in = (const float2*)d_in[0];
    float* out = (float*)d_out;
    dim3 grid(NUM_FRAME, NBF);
    acg_kernel<<<grid, 256>>>(in, out);
}

// round 4
// speedup vs baseline: 1.5031x; 1.0125x over previous
#include <cuda_runtime.h>
#include <cstdint>

#define NUM_FRAME 300
#define LEN_FRAME 512
#define T_LEN     20000
#define NBF       200          // 4 * 50
#define NLAG      256          // LEN_FRAME / 2

typedef unsigned long long ull;

// Packed fp32x2 ops (sm_100+). Lanes = the two channels.
__device__ __forceinline__ ull ffma2(ull a, ull b, ull c) {
    ull d;
    asm("fma.rn.f32x2 %0, %1, %2, %3;" : "=l"(d) : "l"(a), "l"(b), "l"(c));
    return d;
}
__device__ __forceinline__ ull fadd2(ull a, ull b) {
    ull d;
    asm("add.rn.f32x2 %0, %1, %2;" : "=l"(d) : "l"(a), "l"(b));
    return d;
}
__device__ __forceinline__ float2 ull_as_f2(ull u) {
    float2 f;
    f.x = __uint_as_float((unsigned int)(u & 0xffffffffull));
    f.y = __uint_as_float((unsigned int)(u >> 32));
    return f;
}

// One block per (bf, frame). 256 threads = 8 warps = 16 n-partitions of 32.
//  - sw[384] ulonglong2: 768 channel-packed windowed samples (circular tail
//    duplicated), XOR-swizzled at 16B-unit granularity: phys = u ^ ((u>>3)&7).
//  - lane layout: warp wp, half = lane>>4, partition pid = 2*wp+half owns
//    n in [32*pid, 32*pid+32); h = lane&15 owns lags 16h..16h+15.
//    Sliding 20-register window: 64 FFMA2 per 4 LDS.128, addresses reduced to
//    1 LOP3 + 1 LEA (+1 XOR) per load pair via compile-time (grp, c2) split.
//  - halves combined via shfl_xor(16) + f32x2 add; 8-way smem reduction.
__global__ __launch_bounds__(256, 2)
void acg_kernel(const float2* __restrict__ in, float* __restrict__ out) {
    __shared__ ulonglong2 sw[384];
    __shared__ ulonglong2 red2[1024];   // 8 partitions x 256 lags (packed)
    __shared__ float2 snorm;

    const int frame = blockIdx.x;
    const int bf    = blockIdx.y;
    const int tid   = threadIdx.x;

    // starts = linspace(0, T-L, 300).astype(int64)  ==  (i*(T-L))/299 exactly
    const int start = (frame * (T_LEN - LEN_FRAME)) / (NUM_FRAME - 1);

    // ---- load + Hann window, swizzled store ----
    const float2* basep = in + (size_t)bf * T_LEN + start;
    ull* s8 = (ull*)sw;
    #pragma unroll
    for (int i = tid; i < LEN_FRAME; i += 256) {
        float2 v = basep[i];
        float wnd = 0.5f - 0.5f * cospif((float)i * (1.0f / 256.0f));
        ull pv = ((ull)__float_as_uint(v.y * wnd) << 32) | __float_as_uint(v.x * wnd);
        int u = i >> 1;
        s8[((u ^ ((u >> 3) & 7)) << 1) | (i & 1)] = pv;
        if (i < NLAG) {                              // duplicated circular tail
            int i2 = i + LEN_FRAME, u2 = i2 >> 1;
            s8[((u2 ^ ((u2 >> 3) & 7)) << 1) | (i2 & 1)] = pv;
        }
    }
    __syncthreads();

    const int wp   = tid >> 5;
    const int q    = tid & 31;
    const int half = q >> 4;
    const int h    = q & 15;
    const int pid  = (wp << 1) | half;        // n-partition 0..15
    const int ub0  = (pid << 4) + (h << 3);   // unit of s[32*pid + 16*h]; low3 = 0
    const int g0   = ub0 >> 3;

    const ulonglong2* swp = sw + ub0;         // strided window base
    const ulonglong2* bp  = sw + (pid << 4);  // broadcast base (low3 = 0)
    const int gA  = g0 & 7;                   // prologue group
    const int gS1 = (g0 + 1) & 7;             // strided, iters 0..3
    const int gS2 = (g0 + 2) & 7;             // strided, iters 4..7
    const int gB0 = (pid << 1) & 7;           // broadcast, iters 0..3
    const int gB1 = ((pid << 1) + 1) & 7;     // broadcast, iters 4..7

    ull wr[20], acc[16];
    #pragma unroll
    for (int k = 0; k < 16; ++k) acc[k] = 0ull;

    // prologue: wr[0..15] = s[m0 .. m0+15]  (units ub0 .. ub0+7, same group)
    #pragma unroll
    for (int c2 = 0; c2 < 8; c2 += 2) {
        ulonglong2 t0 = swp[c2 ^ gA];
        ulonglong2 t1 = swp[(c2 + 1) ^ gA];
        wr[2 * c2 + 0] = t0.x; wr[2 * c2 + 1] = t0.y;
        wr[2 * c2 + 2] = t1.x; wr[2 * c2 + 3] = t1.y;
    }

    #pragma unroll
    for (int it = 0; it < 8; ++it) {
        const int c2   = (2 * it) & 7;
        const int sOff = (it < 4) ? 8 : 16;     // 8 * grp
        const int gS   = (it < 4) ? gS1 : gS2;
        // strided: wr[16..19] = s[m+16 .. m+19]  (conflict-free)
        ulonglong2 t0 = swp[sOff + (c2 ^ gS)];
        ulonglong2 t1 = swp[sOff + ((c2 + 1) ^ gS)];
        wr[16] = t0.x; wr[17] = t0.y; wr[18] = t1.x; wr[19] = t1.y;

        const int bOff = (it < 4) ? 0 : 8;
        const int gB   = (it < 4) ? gB0 : gB1;
        // broadcast: b0..b3 = s[n .. n+3]
        ulonglong2 tb0 = bp[bOff + (c2 ^ gB)];
        ulonglong2 tb1 = bp[bOff + ((c2 + 1) ^ gB)];
        const ull b0 = tb0.x, b1 = tb0.y, b2 = tb1.x, b3 = tb1.y;

        #pragma unroll
        for (int k = 0; k < 16; ++k) acc[k] = ffma2(b0, wr[k],     acc[k]);
        #pragma unroll
        for (int k = 0; k < 16; ++k) acc[k] = ffma2(b1, wr[k + 1], acc[k]);
        #pragma unroll
        for (int k = 0; k < 16; ++k) acc[k] = ffma2(b2, wr[k + 2], acc[k]);
        #pragma unroll
        for (int k = 0; k < 16; ++k) acc[k] = ffma2(b3, wr[k + 3], acc[k]);

        #pragma unroll
        for (int r = 0; r < 16; ++r) wr[r] = wr[r + 4];
    }

    // ---- combine the two 16-lane halves of each warp (packed f32x2 add) ----
    #pragma unroll
    for (int k = 0; k < 16; ++k)
        acc[k] = fadd2(acc[k], __shfl_xor_sync(0xffffffffu, acc[k], 16));

    // ---- 8-partition smem reduction (swizzled, conflict-free) ----
    if (half == 0) {
        #pragma unroll
        for (int k2 = 0; k2 < 8; ++k2) {
            int r = (wp << 7) + (h << 3) + k2;           // packed-unit index
            red2[r ^ ((r >> 3) & 7)] = make_ulonglong2(acc[2 * k2], acc[2 * k2 + 1]);
        }
    }
    __syncthreads();

    const ull* red8 = (const ull*)red2;
    float chA = 0.0f, chB = 0.0f;
    #pragma unroll
    for (int j = 0; j < 8; ++j) {
        int idx = (j << 8) + tid;
        int u = idx >> 1;
        int pu = u ^ ((u >> 3) & 7);
        float2 v = ull_as_f2(red8[(pu << 1) | (idx & 1)]);
        chA += v.x; chB += v.y;
    }

    // relu
    chA = fmaxf(chA, 0.0f);
    chB = fmaxf(chB, 0.0f);

    // lag-0 norms (thread 0 owns lag 0)
    if (tid == 0) snorm = make_float2(chA, chB);
    __syncthreads();

    float nA = snorm.x; nA = (nA == 0.0f) ? 1.0f : nA;
    float nB = snorm.y; nB = (nB == 0.0f) ? 1.0f : nB;

    const float o = 0.5f * (chA * rsqrtf(nA) + chB * rsqrtf(nB));
    out[((size_t)bf * NUM_FRAME + frame) * NLAG + tid] = o;
}

extern "C" void kernel_launch(void* const* d_in, const int* in_sizes, int n_in,
                              void* d_out, int out_size) {
    (void)in_sizes; (void)n_in; (void)out_size;
    const float2* in = (const float2*)d_in[0];
    float* out = (float*)d_out;
    dim3 grid(NUM_FRAME, NBF);
    acg_kernel<<<grid, 256>>>(in, out);
}

// round 7
// speedup vs baseline: 1.8444x; 1.2271x over previous
#include <cuda_runtime.h>
#include <cstdint>

#define NUM_FRAME 300
#define LEN_FRAME 512
#define T_LEN     20000
#define NBF       200          // 4 * 50
#define NLAG      256          // LEN_FRAME / 2

typedef unsigned long long ull;

// Packed fp32x2 ops (sm_100+). Lanes = the two channels.
__device__ __forceinline__ ull ffma2(ull a, ull b, ull c) {
    ull d;
    asm("fma.rn.f32x2 %0, %1, %2, %3;" : "=l"(d) : "l"(a), "l"(b), "l"(c));
    return d;
}
__device__ __forceinline__ ull fadd2(ull a, ull b) {
    ull d;
    asm("add.rn.f32x2 %0, %1, %2;" : "=l"(d) : "l"(a), "l"(b));
    return d;
}
__device__ __forceinline__ float2 ull_as_f2(ull u) {
    float2 f;
    f.x = __uint_as_float((unsigned int)(u & 0xffffffffull));
    f.y = __uint_as_float((unsigned int)(u >> 32));
    return f;
}

// One block per (bf, frame). 128 threads = 4 warps = 8 n-partitions of 64.
//  - sw[384] ulonglong2: 768 channel-packed windowed samples (circular tail
//    duplicated), XOR-swizzled at 16B-unit granularity: phys = u ^ ((u>>3)&7).
//  - warp w, half = lane>>4 -> partition pid = 2w+half owns n in [64pid,64pid+64);
//    h = lane&15 owns lags 16h..16h+15. Sliding 20-reg window, 16 iterations of
//    n-step 4: 64 FFMA2 per (2 strided + 2 broadcast) LDS.128.
//    Refill at iteration it fetches s[m0+4it+16..m0+4it+19] = window-base units
//    2it+8, 2it+9  ->  group (2it+8)>>3, within-group column (2it)&7.
//  - halves combined via shfl_xor(16); 4-way smem reduction; each thread emits
//    2 lag outputs (tid, tid+128).
__global__ __launch_bounds__(128, 5)
void acg_kernel(const float2* __restrict__ in, float* __restrict__ out) {
    __shared__ ulonglong2 sw[384];
    __shared__ ulonglong2 red2[512];    // 4 partitions x 256 lags (packed pairs)
    __shared__ float2 snorm;

    const int frame = blockIdx.x;
    const int bf    = blockIdx.y;
    const int tid   = threadIdx.x;

    // starts = linspace(0, T-L, 300).astype(int64)  ==  (i*(T-L))/299 exactly
    const int start = (frame * (T_LEN - LEN_FRAME)) / (NUM_FRAME - 1);

    // ---- load + Hann window, swizzled store ----
    const float2* basep = in + (size_t)bf * T_LEN + start;
    ull* s8 = (ull*)sw;
    #pragma unroll
    for (int i = tid; i < LEN_FRAME; i += 128) {
        float2 v = basep[i];
        float wnd = 0.5f - 0.5f * cospif((float)i * (1.0f / 256.0f));
        ull pv = ((ull)__float_as_uint(v.y * wnd) << 32) | __float_as_uint(v.x * wnd);
        int u = i >> 1;
        s8[((u ^ ((u >> 3) & 7)) << 1) | (i & 1)] = pv;
        if (i < NLAG) {                              // duplicated circular tail
            int i2 = i + LEN_FRAME, u2 = i2 >> 1;
            s8[((u2 ^ ((u2 >> 3) & 7)) << 1) | (i2 & 1)] = pv;
        }
    }
    __syncthreads();

    const int w    = tid >> 5;                // warp 0..3
    const int q    = tid & 31;
    const int half = q >> 4;
    const int h    = q & 15;
    const int pid  = (w << 1) | half;         // n-partition 0..7 (n0 = 64*pid)
    const int ub0  = (pid << 5) + (h << 3);   // unit of s[64*pid + 16*h]; low3 = 0

    const ulonglong2* swp = sw + ub0;         // strided window base
    const ulonglong2* bp  = sw + (pid << 5);  // broadcast base (low3 = 0)
    const int g0 = ub0 >> 3;
    // strided-refill group masks: group g0+sGrp, sGrp = (2it+8)>>3 in {1..4}
    int gS[5];
    #pragma unroll
    for (int k = 0; k < 5; ++k) gS[k] = (g0 + k) & 7;
    // broadcast group masks: group 4*pid + bGrp, bGrp = (2it)>>3 in {0..3}
    int gB[4];
    #pragma unroll
    for (int k = 0; k < 4; ++k) gB[k] = ((pid << 2) + k) & 7;

    ull wr[20], acc[16];
    #pragma unroll
    for (int k = 0; k < 16; ++k) acc[k] = 0ull;

    // prologue: wr[0..15] = s[m0 .. m0+15]  (units ub0..ub0+7, group g0)
    {
        const int gA = g0 & 7;
        #pragma unroll
        for (int c2 = 0; c2 < 8; ++c2) {
            ulonglong2 t = swp[c2 ^ gA];
            wr[2 * c2] = t.x; wr[2 * c2 + 1] = t.y;
        }
    }

    #pragma unroll
    for (int it = 0; it < 16; ++it) {
        const int c2   = (2 * it) & 7;            // even, so c2+1 <= 7
        const int sGrp = (2 * it + 8) >> 3;       // compile-time, 1..4
        const int sOff = sGrp << 3;
        const int gSs  = gS[sGrp];
        // strided refill: wr[16..19] = s[m+16 .. m+19] (units 2it+8, 2it+9)
        ulonglong2 t0 = swp[sOff + (c2 ^ gSs)];
        ulonglong2 t1 = swp[sOff + ((c2 + 1) ^ gSs)];
        wr[16] = t0.x; wr[17] = t0.y; wr[18] = t1.x; wr[19] = t1.y;

        const int bGrp = (2 * it) >> 3;           // compile-time, 0..3
        const int bOff = bGrp << 3;
        const int gBb  = gB[bGrp];
        // broadcast: b0..b3 = s[n .. n+3] (units 2it, 2it+1)
        ulonglong2 tb0 = bp[bOff + (c2 ^ gBb)];
        ulonglong2 tb1 = bp[bOff + ((c2 + 1) ^ gBb)];
        const ull b0 = tb0.x, b1 = tb0.y, b2 = tb1.x, b3 = tb1.y;

        #pragma unroll
        for (int k = 0; k < 16; ++k) acc[k] = ffma2(b0, wr[k],     acc[k]);
        #pragma unroll
        for (int k = 0; k < 16; ++k) acc[k] = ffma2(b1, wr[k + 1], acc[k]);
        #pragma unroll
        for (int k = 0; k < 16; ++k) acc[k] = ffma2(b2, wr[k + 2], acc[k]);
        #pragma unroll
        for (int k = 0; k < 16; ++k) acc[k] = ffma2(b3, wr[k + 3], acc[k]);

        #pragma unroll
        for (int r = 0; r < 16; ++r) wr[r] = wr[r + 4];
    }

    // ---- combine the two 16-lane halves of each warp (packed f32x2 add) ----
    #pragma unroll
    for (int k = 0; k < 16; ++k)
        acc[k] = fadd2(acc[k], __shfl_xor_sync(0xffffffffu, acc[k], 16));

    // ---- 4-partition smem reduction (swizzled, conflict-free) ----
    if (half == 0) {
        #pragma unroll
        for (int k2 = 0; k2 < 8; ++k2) {
            int r = (w << 7) + (h << 3) + k2;            // packed-pair index
            red2[r ^ ((r >> 3) & 7)] = make_ulonglong2(acc[2 * k2], acc[2 * k2 + 1]);
        }
    }
    __syncthreads();

    const ull* red8 = (const ull*)red2;
    float cA0 = 0.0f, cB0 = 0.0f, cA1 = 0.0f, cB1 = 0.0f;
    #pragma unroll
    for (int j = 0; j < 4; ++j) {
        int idx0 = (j << 8) + tid;
        int u0 = idx0 >> 1, pu0 = u0 ^ ((u0 >> 3) & 7);
        float2 v0 = ull_as_f2(red8[(pu0 << 1) | (idx0 & 1)]);
        cA0 += v0.x; cB0 += v0.y;
        int idx1 = idx0 + 128;
        int u1 = idx1 >> 1, pu1 = u1 ^ ((u1 >> 3) & 7);
        float2 v1 = ull_as_f2(red8[(pu1 << 1) | (idx1 & 1)]);
        cA1 += v1.x; cB1 += v1.y;
    }

    // relu
    cA0 = fmaxf(cA0, 0.0f); cB0 = fmaxf(cB0, 0.0f);
    cA1 = fmaxf(cA1, 0.0f); cB1 = fmaxf(cB1, 0.0f);

    // lag-0 norms (thread 0's first lag is lag 0)
    if (tid == 0) snorm = make_float2(cA0, cB0);
    __syncthreads();

    float nA = snorm.x; nA = (nA == 0.0f) ? 1.0f : nA;
    float nB = snorm.y; nB = (nB == 0.0f) ? 1.0f : nB;
    const float rA = rsqrtf(nA), rB = rsqrtf(nB);

    float* ob = out + ((size_t)bf * NUM_FRAME + frame) * NLAG;
    ob[tid]       = 0.5f * (cA0 * rA + cB0 * rB);
    ob[tid + 128] = 0.5f * (cA1 * rA + cB1 * rB);
}

extern "C" void kernel_launch(void* const* d_in, const int* in_sizes, int n_in,
                              void* d_out, int out_size) {
    (void)in_sizes; (void)n_in; (void)out_size;
    const float2* in = (const float2*)d_in[0];
    float* out = (float*)d_out;
    dim3 grid(NUM_FRAME, NBF);
    acg_kernel<<<grid, 128>>>(in, out);
}

// round 8
// speedup vs baseline: 2.7876x; 1.5114x over previous
#include <cuda_runtime.h>
#include <cstdint>

#define NUM_FRAME 300
#define LEN_FRAME 512
#define T_LEN     20000
#define NBF       200          // 4 * 50
#define NLAG      256          // LEN_FRAME / 2

// Padded smem index: 1 extra slot per 16 float2 kills power-of-2-stride
// bank conflicts (butterfly data and twiddle gathers).
#define IX(i) ((i) + ((i) >> 4))

// One block per (bf, frame). 128 threads.
// z[n] = (a[n]+i b[n]) * hann[n]  (channels packed as one complex signal).
// Forward radix-2 DIF (natural -> bit-reversed), Hermitian split + |.|^2 in the
// bit-reversed domain (pairing via double bit-reversal), inverse radix-2 DIT
// with conjugated twiddles (bit-reversed -> natural). IDFT(Pa + i Pb) =
// acf_a + i acf_b since Pa, Pb are real-even. 1/512 folded into the pointwise.
__global__ __launch_bounds__(128, 8)
void acg_fft_kernel(const float2* __restrict__ in, float* __restrict__ out) {
    __shared__ float2 X[544];   // 512 + pad
    __shared__ float2 Y[544];
    __shared__ float2 W[272];   // 256 twiddles + pad: W[t] = exp(-2*pi*i*t/512)

    const int frame = blockIdx.x;
    const int bf    = blockIdx.y;
    const int tid   = threadIdx.x;

    // starts = linspace(0, T-L, 300).astype(int64) == (i*(T-L))/299 exactly
    const int start = (frame * (T_LEN - LEN_FRAME)) / (NUM_FRAME - 1);
    const float2* basep = in + (size_t)bf * T_LEN + start;

    // ---- twiddle table ----
    #pragma unroll
    for (int t = tid; t < 256; t += 128) {
        float sv, cv;
        sincospif((float)t * (1.0f / 256.0f), &sv, &cv);
        W[IX(t)] = make_float2(cv, -sv);
    }
    // ---- load + Hann window ----
    #pragma unroll
    for (int i = tid; i < LEN_FRAME; i += 128) {
        float2 v = basep[i];
        float wnd = 0.5f - 0.5f * cospif((float)i * (1.0f / 256.0f));
        X[IX(i)] = make_float2(v.x * wnd, v.y * wnd);
    }
    __syncthreads();

    // ---- forward FFT: radix-2 DIF, output bit-reversed ----
    #pragma unroll
    for (int s = 0; s < 9; ++s) {
        const int lm = 8 - s;          // log2(m); m = half-span
        const int m  = 1 << lm;
        #pragma unroll
        for (int bb = 0; bb < 2; ++bb) {
            const int b  = tid + (bb << 7);          // butterfly id 0..255
            const int j  = b & (m - 1);
            const int i0 = ((b >> lm) << (lm + 1)) + j;
            const int i1 = i0 + m;
            float2 u = X[IX(i0)], v = X[IX(i1)];
            float2 tw = W[IX(j << s)];               // exponent j*2^s < 256
            float dx = u.x - v.x, dy = u.y - v.y;
            X[IX(i0)] = make_float2(u.x + v.x, u.y + v.y);
            X[IX(i1)] = make_float2(dx * tw.x - dy * tw.y,
                                    dx * tw.y + dy * tw.x);
        }
        __syncthreads();
    }

    // ---- pointwise: Q[k] = (|Xa[k]|^2 + i*|Xb[k]|^2)/512, bit-reversed domain ----
    // Storage p holds Z[rev9(p)]. Partner of k is (512-k)&511 at storage
    // q = rev9((512-rev9(p)) & 511). Xa=(Zp+conj(Zq))/2, Xb=(Zp-conj(Zq))/(2i).
    #pragma unroll
    for (int r = 0; r < 4; ++r) {
        const int p  = tid + (r << 7);
        const int k  = (int)(__brev((unsigned)p) >> 23);
        const int kp = (512 - k) & 511;
        const int qq = (int)(__brev((unsigned)kp) >> 23);
        float2 Zp = X[IX(p)], Zq = X[IX(qq)];
        float ar = 0.5f * (Zp.x + Zq.x);
        float ai = 0.5f * (Zp.y - Zq.y);
        float br = 0.5f * (Zp.y + Zq.y);
        float bi = 0.5f * (Zq.x - Zp.x);
        Y[IX(p)] = make_float2((ar * ar + ai * ai) * (1.0f / 512.0f),
                               (br * br + bi * bi) * (1.0f / 512.0f));
    }
    __syncthreads();

    // ---- inverse FFT: radix-2 DIT, bit-reversed input -> natural output,
    //      conjugated twiddles (computes sum Q[k] e^{+2*pi*i*k*l/N}) ----
    #pragma unroll
    for (int s = 0; s < 9; ++s) {
        const int m = 1 << s;
        #pragma unroll
        for (int bb = 0; bb < 2; ++bb) {
            const int b  = tid + (bb << 7);
            const int j  = b & (m - 1);
            const int i0 = ((b >> s) << (s + 1)) + j;
            const int i1 = i0 + m;
            float2 u = Y[IX(i0)], v = Y[IX(i1)];
            float2 tw = W[IX(j << (8 - s))];         // exponent j*2^(8-s) < 256
            // t = v * conj(tw)
            float tx = v.x * tw.x + v.y * tw.y;
            float ty = v.y * tw.x - v.x * tw.y;
            Y[IX(i0)] = make_float2(u.x + tx, u.y + ty);
            Y[IX(i1)] = make_float2(u.x - tx, u.y - ty);
        }
        __syncthreads();
    }

    // ---- epilogue: relu, sqrt-normalize by lag-0, channel mean ----
    const float2 a0 = Y[IX(0)];
    float nA = fmaxf(a0.x, 0.0f); if (nA == 0.0f) nA = 1.0f;
    float nB = fmaxf(a0.y, 0.0f); if (nB == 0.0f) nB = 1.0f;
    const float rA = rsqrtf(nA), rB = rsqrtf(nB);

    float* ob = out + ((size_t)bf * NUM_FRAME + frame) * NLAG;
    #pragma unroll
    for (int r = 0; r < 2; ++r) {
        const int l = tid + (r << 7);
        float2 v = Y[IX(l)];
        ob[l] = 0.5f * (fmaxf(v.x, 0.0f) * rA + fmaxf(v.y, 0.0f) * rB);
    }
}

extern "C" void kernel_launch(void* const* d_in, const int* in_sizes, int n_in,
                              void* d_out, int out_size) {
    (void)in_sizes; (void)n_in; (void)out_size;
    const float2* in = (const float2*)d_in[0];
    float* out = (float*)d_out;
    dim3 grid(NUM_FRAME, NBF);
    acg_fft_kernel<<<grid, 128>>>(in, out);
}